// round 8
// baseline (speedup 1.0000x reference)
#include <cuda_runtime.h>
#include <cstdint>
#include <cstddef>

#define BB   32
#define NN   1024
#define DIMV 512
#define HH   8
#define KDV  64
#define DV   256
#define DHV  2048
#define QKVV 3072

// ---------------- scratch (device globals; allocation-free) ----------------
__device__ float g_xn[(size_t)BB * NN * DIMV];        //  64 MB
__device__ float g_qkv[(size_t)BB * NN * QKVV];       // 384 MB
__device__ float g_av[(size_t)BB * NN * DHV];         // 256 MB (b, q, h, d)
__device__ float g_biasmat[(size_t)HH * NN * NN];     //  32 MB (h, q, k)

// ---------------- helpers ----------------
__device__ __forceinline__ uint32_t f2tf32(float x) {
    uint32_t r;
    asm("cvt.rna.tf32.f32 %0, %1;" : "=r"(r) : "f"(x));
    return r;
}

__device__ __forceinline__ void mma_tf32(float c[4], const uint32_t a[4],
                                         const uint32_t b[2]) {
    asm volatile(
        "mma.sync.aligned.m16n8k8.row.col.f32.tf32.tf32.f32 "
        "{%0,%1,%2,%3}, {%4,%5,%6,%7}, {%8,%9}, {%0,%1,%2,%3};\n"
        : "+f"(c[0]), "+f"(c[1]), "+f"(c[2]), "+f"(c[3])
        : "r"(a[0]), "r"(a[1]), "r"(a[2]), "r"(a[3]), "r"(b[0]), "r"(b[1]));
}

__device__ __forceinline__ void cp16(void* smem_dst, const void* gsrc) {
    uint32_t d = (uint32_t)__cvta_generic_to_shared(smem_dst);
    asm volatile("cp.async.cg.shared.global [%0], [%1], 16;\n"
                 :: "r"(d), "l"(gsrc));
}
#define CP_COMMIT() asm volatile("cp.async.commit_group;\n" ::: "memory")
#define CP_WAIT0()  asm volatile("cp.async.wait_group 0;\n" ::: "memory")
#define CP_WAIT1()  asm volatile("cp.async.wait_group 1;\n" ::: "memory")

// ---------------- LayerNorm ----------------
__global__ void __launch_bounds__(128)
ln_kernel(const float* __restrict__ x, const float* __restrict__ gamma,
          const float* __restrict__ beta) {
    const int row = blockIdx.x;
    const int t = threadIdx.x;
    const float4 v = reinterpret_cast<const float4*>(x)[(size_t)row * (DIMV / 4) + t];
    float s  = v.x + v.y + v.z + v.w;
    float sq = v.x * v.x + v.y * v.y + v.z * v.z + v.w * v.w;
    #pragma unroll
    for (int o = 16; o > 0; o >>= 1) {
        s  += __shfl_xor_sync(0xffffffffu, s, o);
        sq += __shfl_xor_sync(0xffffffffu, sq, o);
    }
    __shared__ float ss[4], ssq[4];
    const int w = t >> 5, l = t & 31;
    if (l == 0) { ss[w] = s; ssq[w] = sq; }
    __syncthreads();
    if (t == 0) {
        float S  = ss[0] + ss[1] + ss[2] + ss[3];
        float SQ = ssq[0] + ssq[1] + ssq[2] + ssq[3];
        float mu = S * (1.0f / DIMV);
        float var = SQ * (1.0f / DIMV) - mu * mu;
        ss[0]  = mu;
        ssq[0] = rsqrtf(var + 1e-5f);
    }
    __syncthreads();
    const float mu = ss[0], rstd = ssq[0];
    const float4 g  = reinterpret_cast<const float4*>(gamma)[t];
    const float4 bt = reinterpret_cast<const float4*>(beta)[t];
    float4 o;
    o.x = (v.x - mu) * rstd * g.x + bt.x;
    o.y = (v.y - mu) * rstd * g.y + bt.y;
    o.z = (v.z - mu) * rstd * g.z + bt.z;
    o.w = (v.w - mu) * rstd * g.w + bt.w;
    reinterpret_cast<float4*>(g_xn)[(size_t)row * (DIMV / 4) + t] = o;
}

// ---------------- dense bias matrix ----------------
__global__ void __launch_bounds__(256)
biasmat_kernel(const float* __restrict__ biases, const int* __restrict__ bidx) {
    const int h = blockIdx.y;
    const size_t i = (size_t)blockIdx.x * 256 + threadIdx.x;
    g_biasmat[(size_t)h * NN * NN + i] = biases[h * 1024 + bidx[i]];
}

// ---------------- tf32 GEMM + bias (qkv, proj), cp.async pipelined ----------
#define AS_ELEMS (128 * 36)
#define STAGE_ELEMS (AS_ELEMS + 32 * 136)
#define MM_SMEM (2 * STAGE_ELEMS * 4)

template<int MODE>   // 0: xn@qkv_w+b -> g_qkv ; 3: av@proj_w+b -> out
__global__ void __launch_bounds__(256, 2)
mm_tf32(const float* __restrict__ Barg, float* __restrict__ Carg,
        const float* __restrict__ biasv) {
    constexpr int LDA  = (MODE == 0) ? DIMV : DHV;
    constexpr int LDB  = (MODE == 0) ? QKVV : DIMV;
    constexpr int LDC  = (MODE == 0) ? QKVV : DIMV;
    constexpr int KDIM = (MODE == 0) ? DIMV : DHV;
    constexpr int NK   = KDIM / 32;

    extern __shared__ float sm[];

    const int tid = threadIdx.x;
    const int m0 = blockIdx.y * 128;
    const int n0 = blockIdx.x * 128;

    const float* Ap = (MODE == 0) ? g_xn : g_av;
    const float* Bp = Barg;
    float* Cp = (MODE == 0) ? g_qkv : Carg;

    const int wid = tid >> 5, lane = tid & 31;
    const int wm = wid >> 1, wn = wid & 1;
    const int grp = lane >> 2, qd = lane & 3;

    const int ar = tid >> 3, ac = (tid & 7) * 4;
    const int br = tid >> 5, bc = (tid & 31) * 4;

    auto issue_tile = [&](int kt) {
        float* As = sm + (kt & 1) * STAGE_ELEMS;
        float* Bs = As + AS_ELEMS;
        const int k0 = kt * 32;
        #pragma unroll
        for (int i = 0; i < 4; ++i) {
            const int r = ar + i * 32;
            cp16(&As[r * 36 + ac], &Ap[(size_t)(m0 + r) * LDA + k0 + ac]);
        }
        #pragma unroll
        for (int i = 0; i < 4; ++i) {
            const int r = br + i * 8;
            cp16(&Bs[r * 136 + bc], &Bp[(size_t)(k0 + r) * LDB + n0 + bc]);
        }
    };

    float acc[2][8][4] = {};

    issue_tile(0); CP_COMMIT();
    issue_tile(1); CP_COMMIT();

    for (int kt = 0; kt < NK; ++kt) {
        CP_WAIT1();
        __syncthreads();
        const float* As = sm + (kt & 1) * STAGE_ELEMS;
        const float* Bs = As + AS_ELEMS;
        #pragma unroll
        for (int ks = 0; ks < 4; ++ks) {
            const int kc = ks * 8 + qd;
            uint32_t af[2][4];
            #pragma unroll
            for (int mt = 0; mt < 2; ++mt) {
                const int mr = wm * 32 + mt * 16 + grp;
                af[mt][0] = f2tf32(As[mr * 36 + kc]);
                af[mt][1] = f2tf32(As[(mr + 8) * 36 + kc]);
                af[mt][2] = f2tf32(As[mr * 36 + kc + 4]);
                af[mt][3] = f2tf32(As[(mr + 8) * 36 + kc + 4]);
            }
            uint32_t bf[8][2];
            #pragma unroll
            for (int nt = 0; nt < 8; ++nt) {
                const int nc = wn * 64 + nt * 8 + grp;
                bf[nt][0] = f2tf32(Bs[kc * 136 + nc]);
                bf[nt][1] = f2tf32(Bs[(kc + 4) * 136 + nc]);
            }
            #pragma unroll
            for (int mt = 0; mt < 2; ++mt)
                #pragma unroll
                for (int nt = 0; nt < 8; ++nt)
                    mma_tf32(acc[mt][nt], af[mt], bf[nt]);
        }
        __syncthreads();
        if (kt + 2 < NK) issue_tile(kt + 2);
        CP_COMMIT();
    }

    #pragma unroll
    for (int mt = 0; mt < 2; ++mt) {
        #pragma unroll
        for (int nt = 0; nt < 8; ++nt) {
            const int r0 = m0 + wm * 32 + mt * 16 + grp;
            const int c0 = n0 + wn * 64 + nt * 8 + 2 * qd;
            const float b0 = biasv[c0], b1 = biasv[c0 + 1];
            *reinterpret_cast<float2*>(&Cp[(size_t)r0 * LDC + c0]) =
                make_float2(acc[mt][nt][0] + b0, acc[mt][nt][1] + b1);
            *reinterpret_cast<float2*>(&Cp[(size_t)(r0 + 8) * LDC + c0]) =
                make_float2(acc[mt][nt][2] + b0, acc[mt][nt][3] + b1);
        }
    }
}

// ---------------- fused flash attention (register-resident softmax) --------
// grid (8 q-tiles, 256 bz), 256 threads / 8 warps; warp owns 16 q-rows.
// k-tile 64; K/V double-buffered cp.async; S, P, O in registers.
// smem: Ks[2][64][68] at 0; Vs[2][64][264] at 8704 floats. (166 KB)
#define KS_STR 68
#define VS_STR 264
#define VS_BASE (2 * 64 * KS_STR)
#define FL_SMEM ((VS_BASE + 2 * 64 * VS_STR) * 4)

__global__ void __launch_bounds__(256, 1)
flash_kernel() {
    extern __shared__ float sm[];

    const int bz = blockIdx.y;
    const int b = bz >> 3, h = bz & 7;
    const int q0 = blockIdx.x * 128;
    const int tid = threadIdx.x;
    const int w = tid >> 5, lane = tid & 31;
    const int grp = lane >> 2, qd = lane & 3;

    const float* qbase = g_qkv + (size_t)b * NN * QKVV + h * 384;
    const float* kbase = qbase + 64;
    const float* vbase = qbase + 128;
    const float* bm = g_biasmat + (size_t)h * NN * NN;

    // ---- load Q tile (128 x 64): 2048 16B chunks, 8 per thread ----
    #pragma unroll
    for (int i = 0; i < 8; ++i) {
        const int idx = tid + i * 256;
        const int row = idx >> 4, c4 = (idx & 15) * 4;
        cp16(&sm[row * KS_STR + c4], &qbase[(size_t)(q0 + row) * QKVV + c4]);
    }
    CP_COMMIT(); CP_WAIT0();
    __syncthreads();

    // ---- extract Q fragments (warp rows 16w .. 16w+15) ----
    uint32_t aq[8][4];
    #pragma unroll
    for (int ks = 0; ks < 8; ++ks) {
        const int mr = 16 * w + grp;
        const int kc = ks * 8 + qd;
        aq[ks][0] = f2tf32(sm[mr * KS_STR + kc]);
        aq[ks][1] = f2tf32(sm[(mr + 8) * KS_STR + kc]);
        aq[ks][2] = f2tf32(sm[mr * KS_STR + kc + 4]);
        aq[ks][3] = f2tf32(sm[(mr + 8) * KS_STR + kc + 4]);
    }
    __syncthreads();

    // ---- K/V tile issue (K: 64x64 = 1024 chunks; V: 64x256 = 4096 chunks) --
    auto issue_kv = [&](int kt) {
        float* Ks = sm + (kt & 1) * 64 * KS_STR;
        float* Vs = sm + VS_BASE + (kt & 1) * 64 * VS_STR;
        const int k0 = kt * 64;
        #pragma unroll
        for (int i = 0; i < 4; ++i) {
            const int idx = tid + i * 256;
            const int row = idx >> 4, c4 = (idx & 15) * 4;
            cp16(&Ks[row * KS_STR + c4],
                 &kbase[(size_t)(k0 + row) * QKVV + c4]);
        }
        #pragma unroll
        for (int i = 0; i < 16; ++i) {
            const int idx = tid + i * 256;
            const int row = idx >> 6, c4 = (idx & 63) * 4;
            cp16(&Vs[row * VS_STR + c4],
                 &vbase[(size_t)(k0 + row) * QKVV + c4]);
        }
    };

    issue_kv(0); CP_COMMIT();
    issue_kv(1); CP_COMMIT();

    float oacc[32][4] = {};
    float m0 = -1e30f, m1 = -1e30f, l0 = 0.0f, l1 = 0.0f;

    const int srcA = (lane & ~3) | (qd >> 1);
    const int srcB = srcA + 2;
    const bool sel = (qd & 1);

    for (int kt = 0; kt < 16; ++kt) {
        CP_WAIT1();
        __syncthreads();
        const float* Ks = sm + (kt & 1) * 64 * KS_STR;
        const float* Vs = sm + VS_BASE + (kt & 1) * 64 * VS_STR;
        const int k0 = kt * 64;

        // ---- S = Q @ K^T (16 x 64 per warp) ----
        float sacc[8][4] = {};
        #pragma unroll
        for (int ks = 0; ks < 8; ++ks) {
            const int kc = ks * 8 + qd;
            #pragma unroll
            for (int nf = 0; nf < 8; ++nf) {
                const int key = nf * 8 + grp;
                uint32_t bf[2];
                bf[0] = f2tf32(Ks[key * KS_STR + kc]);
                bf[1] = f2tf32(Ks[key * KS_STR + kc + 4]);
                mma_tf32(sacc[nf], aq[ks], bf);
            }
        }

        // ---- scale + bias ----
        const int r0 = q0 + 16 * w + grp;
        #pragma unroll
        for (int nf = 0; nf < 8; ++nf) {
            const int c = k0 + nf * 8 + 2 * qd;
            const float2 b0 = *reinterpret_cast<const float2*>(
                &bm[(size_t)r0 * NN + c]);
            const float2 b1 = *reinterpret_cast<const float2*>(
                &bm[(size_t)(r0 + 8) * NN + c]);
            sacc[nf][0] = sacc[nf][0] * 0.125f + b0.x;
            sacc[nf][1] = sacc[nf][1] * 0.125f + b0.y;
            sacc[nf][2] = sacc[nf][2] * 0.125f + b1.x;
            sacc[nf][3] = sacc[nf][3] * 0.125f + b1.y;
        }

        // ---- online softmax in registers ----
        float mx0 = sacc[0][0], mx1 = sacc[0][2];
        #pragma unroll
        for (int nf = 0; nf < 8; ++nf) {
            mx0 = fmaxf(mx0, fmaxf(sacc[nf][0], sacc[nf][1]));
            mx1 = fmaxf(mx1, fmaxf(sacc[nf][2], sacc[nf][3]));
        }
        mx0 = fmaxf(mx0, __shfl_xor_sync(0xffffffffu, mx0, 1));
        mx0 = fmaxf(mx0, __shfl_xor_sync(0xffffffffu, mx0, 2));
        mx1 = fmaxf(mx1, __shfl_xor_sync(0xffffffffu, mx1, 1));
        mx1 = fmaxf(mx1, __shfl_xor_sync(0xffffffffu, mx1, 2));
        const float mn0 = fmaxf(m0, mx0);
        const float mn1 = fmaxf(m1, mx1);
        const float fac0 = __expf(m0 - mn0);
        const float fac1 = __expf(m1 - mn1);
        float sum0 = 0.0f, sum1 = 0.0f;
        #pragma unroll
        for (int nf = 0; nf < 8; ++nf) {
            sacc[nf][0] = __expf(sacc[nf][0] - mn0);
            sacc[nf][1] = __expf(sacc[nf][1] - mn0);
            sacc[nf][2] = __expf(sacc[nf][2] - mn1);
            sacc[nf][3] = __expf(sacc[nf][3] - mn1);
            sum0 += sacc[nf][0] + sacc[nf][1];
            sum1 += sacc[nf][2] + sacc[nf][3];
        }
        sum0 += __shfl_xor_sync(0xffffffffu, sum0, 1);
        sum0 += __shfl_xor_sync(0xffffffffu, sum0, 2);
        sum1 += __shfl_xor_sync(0xffffffffu, sum1, 1);
        sum1 += __shfl_xor_sync(0xffffffffu, sum1, 2);
        l0 = l0 * fac0 + sum0;
        l1 = l1 * fac1 + sum1;
        m0 = mn0; m1 = mn1;

        // ---- rescale O ----
        #pragma unroll
        for (int nf = 0; nf < 32; ++nf) {
            oacc[nf][0] *= fac0; oacc[nf][1] *= fac0;
            oacc[nf][2] *= fac1; oacc[nf][3] *= fac1;
        }

        // ---- transpose P fragments (C-layout -> A-layout) via quad shfl ----
        uint32_t ap[8][4];
        #pragma unroll
        for (int f = 0; f < 8; ++f) {
            const float x0 = __shfl_sync(0xffffffffu, sacc[f][0], srcA);
            const float x1 = __shfl_sync(0xffffffffu, sacc[f][1], srcA);
            const float y0 = __shfl_sync(0xffffffffu, sacc[f][0], srcB);
            const float y1 = __shfl_sync(0xffffffffu, sacc[f][1], srcB);
            const float x2 = __shfl_sync(0xffffffffu, sacc[f][2], srcA);
            const float x3 = __shfl_sync(0xffffffffu, sacc[f][3], srcA);
            const float y2 = __shfl_sync(0xffffffffu, sacc[f][2], srcB);
            const float y3 = __shfl_sync(0xffffffffu, sacc[f][3], srcB);
            ap[f][0] = f2tf32(sel ? x1 : x0);
            ap[f][2] = f2tf32(sel ? y1 : y0);
            ap[f][1] = f2tf32(sel ? x3 : x2);
            ap[f][3] = f2tf32(sel ? y3 : y2);
        }

        // ---- O += P @ V (16 x 256 per warp) ----
        #pragma unroll
        for (int ks = 0; ks < 8; ++ks) {
            const int kr = ks * 8 + qd;
            #pragma unroll
            for (int nf = 0; nf < 32; ++nf) {
                const int nc = nf * 8 + grp;
                uint32_t bf[2];
                bf[0] = f2tf32(Vs[kr * VS_STR + nc]);
                bf[1] = f2tf32(Vs[(kr + 4) * VS_STR + nc]);
                mma_tf32(oacc[nf], ap[ks], bf);
            }
        }

        __syncthreads();
        if (kt + 2 < 16) issue_kv(kt + 2);
        CP_COMMIT();
    }

    // ---- normalize + write O ----
    const float inv0 = 1.0f / l0;
    const float inv1 = 1.0f / l1;
    const int r0 = q0 + 16 * w + grp;
    float* obase = g_av + (size_t)b * NN * DHV + h * DV;
    #pragma unroll
    for (int nf = 0; nf < 32; ++nf) {
        const int c = nf * 8 + 2 * qd;
        *reinterpret_cast<float2*>(&obase[(size_t)r0 * DHV + c]) =
            make_float2(oacc[nf][0] * inv0, oacc[nf][1] * inv0);
        *reinterpret_cast<float2*>(&obase[(size_t)(r0 + 8) * DHV + c]) =
            make_float2(oacc[nf][2] * inv1, oacc[nf][3] * inv1);
    }
}

// ---------------- launch ----------------
extern "C" void kernel_launch(void* const* d_in, const int* in_sizes, int n_in,
                              void* d_out, int out_size) {
    (void)in_sizes; (void)n_in; (void)out_size;
    const float* x      = (const float*)d_in[0];
    const float* gamma  = (const float*)d_in[1];
    const float* beta   = (const float*)d_in[2];
    const float* qkv_w  = (const float*)d_in[3];
    const float* qkv_b  = (const float*)d_in[4];
    const float* proj_w = (const float*)d_in[5];
    const float* proj_b = (const float*)d_in[6];
    const float* biases = (const float*)d_in[7];
    const int*   bidx   = (const int*)d_in[8];
    float* out = (float*)d_out;

    cudaFuncSetAttribute(mm_tf32<0>, cudaFuncAttributeMaxDynamicSharedMemorySize, MM_SMEM);
    cudaFuncSetAttribute(mm_tf32<3>, cudaFuncAttributeMaxDynamicSharedMemorySize, MM_SMEM);
    cudaFuncSetAttribute(flash_kernel, cudaFuncAttributeMaxDynamicSharedMemorySize, FL_SMEM);

    ln_kernel<<<BB * NN, 128>>>(x, gamma, beta);

    biasmat_kernel<<<dim3(NN * NN / 256, HH), 256>>>(biases, bidx);

    // QKV: [32768 x 512] @ [512 x 3072]
    mm_tf32<0><<<dim3(QKVV / 128, (BB * NN) / 128), 256, MM_SMEM>>>(qkv_w, nullptr, qkv_b);

    // fused attention -> g_av
    flash_kernel<<<dim3(NN / 128, BB * HH), 256, FL_SMEM>>>();

    // proj: [32768 x 2048] @ [2048 x 512]
    mm_tf32<3><<<dim3(DIMV / 128, (BB * NN) / 128), 256, MM_SMEM>>>(proj_w, out, proj_b);
}